// round 14
// baseline (speedup 1.0000x reference)
#include <cuda_runtime.h>
#include <cuda_bf16.h>

// Problem constants (fixed by the dataset)
#define D_CH   256
#define GRID_H 384
#define GRID_W 384
#define TOK_PER_BLK 16

// Token-index map: g_map[r*W+c] = token id. Zero-initialized at module load.
// Validity is determined by coords round-trip (see conv probe), so NO init
// kernel and NO sentinel clear is needed: never-occupied cells stay 0 forever,
// and a 0 only validates if token 0 actually sits at that cell.
__device__ int g_map[GRID_H * GRID_W];

// ---------------------------------------------------------------------------
// Kernel 1: scatter token ids into the map
// ---------------------------------------------------------------------------
__global__ void scatter_kernel(const int* __restrict__ coords, int n) {
    int i = blockIdx.x * blockDim.x + threadIdx.x;
    if (i < n) {
        g_map[coords[2 * i] * GRID_W + coords[2 * i + 1]] = i;
    }
}

// ---------------------------------------------------------------------------
// Kernel 2: gather-conv, (D, N) channel-major output.
//   256 threads = 8 warps; 16 tokens/block, 2 tokens/warp, interleaved.
//   Per-token live taps compacted (deterministic k-order) and padded to the
//   warp-pairwise max with a zero-weight tap (wT row 9 == 0) aimed at the
//   token's own row (L1-hot). The main loop is branch-free with 4 independent
//   LDG.128 per iteration.
// ---------------------------------------------------------------------------
__global__ __launch_bounds__(256, 4) void conv_kernel(
    const float* __restrict__ tokens,   // [N, 256]
    const int*   __restrict__ coords,   // [N, 2]
    const float* __restrict__ weight,   // [256][9]
    const float* __restrict__ bias,     // [256]
    float*       __restrict__ out,      // [256, N]  (channel-major)
    int n)
{
    __shared__ float  wT[10][D_CH];          // wT[tap][channel]; row 9 = zeros
    __shared__ float4 sOut4[TOK_PER_BLK][65];// [token][c4], pad -> bank-clean
    __shared__ int    ent[TOK_PER_BLK][9];   // compacted (j<<4)|k, padded to 9
    __shared__ int    cnt[TOK_PER_BLK];

    const int tid     = threadIdx.x;
    const int lane    = tid & 31;
    const int warp    = tid >> 5;            // 0..7
    const int tokbase = blockIdx.x * TOK_PER_BLK;

    // --- weights: wT[k][d] = weight[d*9+k]; wT[9][d] = 0 ---
    #pragma unroll
    for (int i = tid; i < 10 * D_CH; i += 256) {
        int d = i & 255;
        int k = i >> 8;
        wT[k][d] = (k < 9) ? weight[d * 9 + k] : 0.0f;
    }

    // --- neighbor probes: 16 tokens x 9 taps, validated by coords round-trip ---
    if (tid < TOK_PER_BLK * 9) {
        int t   = tid / 9;
        int k   = tid % 9;
        int tok = tokbase + t;
        int idx = -1;
        if (tok < n) {
            int r  = coords[2 * tok];
            int c  = coords[2 * tok + 1];
            int rr = r + (k / 3) - 1;
            int cc = c + (k % 3) - 1;
            if (rr >= 0 && rr < GRID_H && cc >= 0 && cc < GRID_W) {
                int j = g_map[rr * GRID_W + cc];
                // validate: cell is occupied by token j iff coords[j]==(rr,cc)
                if (coords[2 * j] == rr && coords[2 * j + 1] == cc) idx = j;
            }
        }
        ent[t][k] = idx;
    }
    __syncthreads();

    // --- deterministic in-place compaction + zero-weight padding to 9 ---
    if (tid < TOK_PER_BLK) {
        int w = 0;
        #pragma unroll
        for (int k = 0; k < 9; k++) {
            int j = ent[tid][k];
            if (j >= 0) ent[tid][w++] = (j << 4) | k;
        }
        cnt[tid] = w;
        int tok = tokbase + tid;
        int own = (tok < n) ? tok : 0;
        int pad = (own << 4) | 9;            // own row, zero weight
        for (; w < 9; w++) ent[tid][w] = pad;
    }
    __syncthreads();

    // --- Phase A: interleaved dual-token gather, branch-free ---
    const float4* tok4  = reinterpret_cast<const float4*>(tokens);
    const float4* bias4 = reinterpret_cast<const float4*>(bias);
    const float4  bA = bias4[lane];          // channels 4l..4l+3
    const float4  bB = bias4[32 + lane];     // channels 128+4l..128+4l+3

    const int t0 = warp * 2;
    const int t1 = t0 + 1;
    const int m0 = cnt[t0], m1 = cnt[t1];
    const int mm = (m0 > m1) ? m0 : m1;      // warp-uniform

    float4 A0 = bA, A1 = bB;                 // token t0
    float4 B0 = bA, B1 = bB;                 // token t1

    for (int e = 0; e < mm; e++) {
        int p0 = ent[t0][e];
        int p1 = ent[t1][e];
        int j0 = p0 >> 4, k0 = p0 & 15;
        int j1 = p1 >> 4, k1 = p1 & 15;

        const float4* s0 = tok4 + (size_t)j0 * (D_CH / 4);
        const float4* s1 = tok4 + (size_t)j1 * (D_CH / 4);
        float4 v00 = s0[lane];
        float4 v01 = s0[32 + lane];
        float4 v10 = s1[lane];
        float4 v11 = s1[32 + lane];

        const float4* w0 = reinterpret_cast<const float4*>(&wT[k0][0]);
        const float4* w1 = reinterpret_cast<const float4*>(&wT[k1][0]);
        float4 w00 = w0[lane];
        float4 w01 = w0[32 + lane];
        float4 w10 = w1[lane];
        float4 w11 = w1[32 + lane];

        A0.x = fmaf(w00.x, v00.x, A0.x); A0.y = fmaf(w00.y, v00.y, A0.y);
        A0.z = fmaf(w00.z, v00.z, A0.z); A0.w = fmaf(w00.w, v00.w, A0.w);
        A1.x = fmaf(w01.x, v01.x, A1.x); A1.y = fmaf(w01.y, v01.y, A1.y);
        A1.z = fmaf(w01.z, v01.z, A1.z); A1.w = fmaf(w01.w, v01.w, A1.w);
        B0.x = fmaf(w10.x, v10.x, B0.x); B0.y = fmaf(w10.y, v10.y, B0.y);
        B0.z = fmaf(w10.z, v10.z, B0.z); B0.w = fmaf(w10.w, v10.w, B0.w);
        B1.x = fmaf(w11.x, v11.x, B1.x); B1.y = fmaf(w11.y, v11.y, B1.y);
        B1.z = fmaf(w11.z, v11.z, B1.z); B1.w = fmaf(w11.w, v11.w, B1.w);
    }

    // --- transpose staging: conflict-free STS.128 (lanes consecutive) ---
    sOut4[t0][lane]      = A0;
    sOut4[t0][32 + lane] = A1;
    sOut4[t1][lane]      = B0;
    sOut4[t1][32 + lane] = B1;
    __syncthreads();

    // --- Phase B: lane = channel; float4 over 4 consecutive tokens ---
    const float* sflat = reinterpret_cast<const float*>(&sOut4[0][0]);
    const int c = warp * 32 + lane;          // 0..255
    #pragma unroll
    for (int g = 0; g < 4; g++) {
        // banks: (t*260 + c) % 32 == (4t + c) % 32 -> distinct per lane
        float4 o;
        o.x = sflat[(4 * g + 0) * 260 + c];
        o.y = sflat[(4 * g + 1) * 260 + c];
        o.z = sflat[(4 * g + 2) * 260 + c];
        o.w = sflat[(4 * g + 3) * 260 + c];
        int tok = tokbase + 4 * g;
        if (tok + 3 < n) {
            *reinterpret_cast<float4*>(out + (size_t)c * n + tok) = o;
        } else {
            if (tok + 0 < n) out[(size_t)c * n + tok + 0] = o.x;
            if (tok + 1 < n) out[(size_t)c * n + tok + 1] = o.y;
            if (tok + 2 < n) out[(size_t)c * n + tok + 2] = o.z;
            if (tok + 3 < n) out[(size_t)c * n + tok + 3] = o.w;
        }
    }
}

// ---------------------------------------------------------------------------
// Launch — inputs bound BY ELEMENT COUNT (robust to metadata.txt ordering):
//   tokens : N*256 = 16,777,216 fp32    coords : 2N = 131,072 int32
//   weight : 2,304 fp32                 bias   : 256 fp32
// Output: fp32 (D, N) flattened (NumPy mixed advanced-indexing semantics).
// ---------------------------------------------------------------------------
extern "C" void kernel_launch(void* const* d_in, const int* in_sizes, int n_in,
                              void* d_out, int out_size) {
    int tok_i = 0;
    for (int i = 1; i < n_in; i++)
        if (in_sizes[i] > in_sizes[tok_i]) tok_i = i;
    const float* tokens = (const float*)d_in[tok_i];
    const int n = in_sizes[tok_i] / D_CH;   // 65536

    const int*   coords = nullptr;
    const float* weight = nullptr;
    const float* bias   = nullptr;
    for (int i = 0; i < n_in; i++) {
        if (i == tok_i) continue;
        const int sz = in_sizes[i];
        if (sz == 2 * n)         coords = (const int*)d_in[i];
        else if (sz == 9 * D_CH) weight = (const float*)d_in[i];
        else if (sz == D_CH)     bias   = (const float*)d_in[i];
    }
    if (!coords || !weight || !bias) {   // defensive positional fallback
        tokens = (const float*)d_in[0];
        coords = (const int*)d_in[1];
        weight = (const float*)d_in[2];
        bias   = (const float*)d_in[3];
    }

    float* out = (float*)d_out;

    // 1. scatter (validity via coords round-trip; no map init needed)
    scatter_kernel<<<(n + 255) / 256, 256>>>(coords, n);
    // 2. conv-gather with transposed output
    int nblocks = (n + TOK_PER_BLK - 1) / TOK_PER_BLK;
    conv_kernel<<<nblocks, 256>>>(tokens, coords, weight, bias, out, n);
}